// round 7
// baseline (speedup 1.0000x reference)
#include <cuda_runtime.h>
#include <cstdint>

// ---------------------------------------------------------------------------
// Problem constants
// ---------------------------------------------------------------------------
#define BATCH   1024
#define D_SZ    384
#define K_WIDE  (D_SZ * D_SZ)      // 147456
#define N_OUT   (2 * D_SZ)         // 768
#define OUT_STR (4 * D_SZ)         // 1536

// ---------------------------------------------------------------------------
// Wide-path GEMM config: M=1024 N=768 K=147456, A = hs x ht generated on-fly
// ---------------------------------------------------------------------------
#define BM      128
#define BN      128
#define BKC     32                  // k-floats per chunk
#define KSPLIT  3
#define KSLICE  (K_WIDE / KSPLIT)   // 49152 = 128 i-values
#define IPG     8                   // i-values per hs staging group
#define NCH     (KSLICE / BKC)      // 1536 chunks per CTA
#define LDT     36                  // row stride words: BKC=32 + 4 pad (conflict-free)
#define NTH     1024                // 32 warps = 8(m) x 4(n), warp tile 16x32
#define NBUF    3

#define B_WORDS   (BN * LDT)            // per B buffer
#define HTS_WORDS (BM * LDT)
#define HSS_WORDS (IPG * BM)
#define SMEM_WORDS (NBUF * B_WORDS + HTS_WORDS + HSS_WORDS)
#define SMEM_BYTES (SMEM_WORDS * 4)     // ~78 KB -> dynamic smem

__device__ __forceinline__ void cp_async16(uint32_t dst, const void* src) {
    asm volatile("cp.async.cg.shared.global [%0], [%1], 16;" :: "r"(dst), "l"(src) : "memory");
}
__device__ __forceinline__ void cp_commit() {
    asm volatile("cp.async.commit_group;" ::: "memory");
}
__device__ __forceinline__ void cp_wait1() {
    asm volatile("cp.async.wait_group 1;" ::: "memory");
}
__device__ __forceinline__ uint32_t smem_u32(const void* p) {
    uint32_t a;
    asm("{ .reg .u64 t; cvta.to.shared.u64 t, %1; cvt.u32.u64 %0, t; }" : "=r"(a) : "l"(p));
    return a;
}
__device__ __forceinline__ float f2tf32(float x) {          // round-to-nearest tf32
    unsigned r;
    asm("cvt.rna.tf32.f32 %0, %1;" : "=r"(r) : "f"(x));
    return __uint_as_float(r);
}

// m16n8k8 tf32 mma (A pre-rounded rna; B HW-truncated from fp32 bits)
__device__ __forceinline__ void mma_tf32(float c[4], const float a[4], float b0, float b1) {
    asm volatile(
        "mma.sync.aligned.m16n8k8.row.col.f32.tf32.tf32.f32 "
        "{%0,%1,%2,%3}, {%4,%5,%6,%7}, {%8,%9}, {%0,%1,%2,%3};\n"
        : "+f"(c[0]), "+f"(c[1]), "+f"(c[2]), "+f"(c[3])
        : "r"(__float_as_uint(a[0])), "r"(__float_as_uint(a[1])),
          "r"(__float_as_uint(a[2])), "r"(__float_as_uint(a[3])),
          "r"(__float_as_uint(b0)), "r"(__float_as_uint(b1)));
}

// ---------------------------------------------------------------------------
// Deep path (passed R1, unchanged):  g = [hs|ht] @ W_L^T + b_L -> out[:,0:768]
// Also initializes out[:,768:1536] = b_L2 for the wide kernel's atomics.
// ---------------------------------------------------------------------------
#define DBM 64
#define DBN 64
#define DBK 16

__global__ __launch_bounds__(256)
void deep_kernel(const float* __restrict__ hs, const float* __restrict__ ht,
                 const float* __restrict__ WL, const float* __restrict__ bL,
                 const float* __restrict__ bL2, float* __restrict__ out)
{
    __shared__ float Xs[DBK][DBM + 8];
    __shared__ float Ws[DBK][DBN + 8];

    const int tid = threadIdx.x;
    const int tx  = tid & 15;
    const int ty  = tid >> 4;
    const int m0  = blockIdx.x * DBM;
    const int n0  = blockIdx.y * DBN;

    float acc[4][4];
#pragma unroll
    for (int i = 0; i < 4; ++i)
#pragma unroll
        for (int j = 0; j < 4; ++j) acc[i][j] = 0.f;

    for (int k0 = 0; k0 < 2 * D_SZ; k0 += DBK) {
        __syncthreads();
#pragma unroll
        for (int q = 0; q < 4; ++q) {
            int e  = tid + 256 * q;
            int kk = e & 15;
            int mm = e >> 4;
            int gk = k0 + kk;
            float xv = (gk < D_SZ) ? hs[(m0 + mm) * D_SZ + gk]
                                   : ht[(m0 + mm) * D_SZ + (gk - D_SZ)];
            Xs[kk][mm] = xv;
            Ws[kk][mm] = WL[(size_t)(n0 + mm) * (2 * D_SZ) + gk];
        }
        __syncthreads();
#pragma unroll
        for (int kk = 0; kk < DBK; ++kk) {
            float4 av = *(const float4*)&Xs[kk][ty * 4];
            float4 bv = *(const float4*)&Ws[kk][tx * 4];
            float a[4] = {av.x, av.y, av.z, av.w};
            float b[4] = {bv.x, bv.y, bv.z, bv.w};
#pragma unroll
            for (int i = 0; i < 4; ++i)
#pragma unroll
                for (int j = 0; j < 4; ++j) acc[i][j] += a[i] * b[j];
        }
    }

#pragma unroll
    for (int i = 0; i < 4; ++i) {
        int row = m0 + ty * 4 + i;
#pragma unroll
        for (int j = 0; j < 4; ++j) {
            int col = n0 + tx * 4 + j;
            out[(size_t)row * OUT_STR + col]         = acc[i][j] + bL[col];
            out[(size_t)row * OUT_STR + N_OUT + col] = bL2[col];
        }
    }
}

// ---------------------------------------------------------------------------
// Wide kernel: 1024 threads = 32 warps (8m x 4n), warp tile 16x32.
// More warps/SMSP (8 vs 4) to hide LDS/CVT->HMMA latency (R6 evidence:
// tensor pipe idle 48% at 4 warps/SMSP; barriers ruled out as the cause).
// A fragments: ht frags (per 128-chunk j-block, registers) x hs scalars
// (per 8-chunk i-group, SMEM), product rounded rna to tf32.
// B: 3-buffer cp.async ring, one 16B copy per thread per chunk.
// Pipeline per chunk ch: wait_group 1 (ch landed) -> sync -> compute buf(ch%3)
// -> issue ch+2 into buf((ch+2)%3) -> commit. Issue target last read at
// iteration ch-1; the barrier at top of ch bounds warp drift.
// ---------------------------------------------------------------------------
__global__ __launch_bounds__(NTH, 1)
void wide_kernel(const float* __restrict__ hs, const float* __restrict__ ht,
                 const float* __restrict__ W2, float* __restrict__ out)
{
    extern __shared__ __align__(16) float smem[];
    float* Bsm = smem;                          // NBUF * BN * LDT
    float* Hts = smem + NBUF * B_WORDS;         // BM * LDT
    float* Hss = Hts + HTS_WORDS;               // IPG * BM

    const int tid  = threadIdx.x;
    const int lane = tid & 31;
    const int warp = tid >> 5;
    const int wm = (warp & 7) * 16;     // warp m offset (8 m-warps)
    const int wn = (warp >> 3) * 32;    // warp n offset (4 n-warps)
    const int r  = lane >> 2;           // 0..7
    const int c  = lane & 3;            // 0..3

    const int m0 = blockIdx.x * BM;
    const int n0 = blockIdx.y * BN;
    const int z  = blockIdx.z;
    const size_t kbase = (size_t)z * KSLICE;
    const int i0 = z * (KSLICE / D_SZ);

    // per-thread B staging coords: 128 rows x 8 float4-segs = 1024 segs, 1 each
    const int srow = tid >> 3;
    const int skv  = (tid & 7) * 4;
    const uint32_t sB = smem_u32(Bsm);

    float acc[4][4];                    // [ni][frag]
#pragma unroll
    for (int ni = 0; ni < 4; ++ni)
#pragma unroll
        for (int q = 0; q < 4; ++q) acc[ni][q] = 0.f;

    float htr[4][4];                    // ht fragments [kstep][frag]

    // ---- prologue: issue chunks 0 and 1 (jc=0, i_loc=pc) ----
#pragma unroll
    for (int pc = 0; pc < 2; ++pc) {
        size_t gcol = kbase + (size_t)pc * D_SZ;
        uint32_t dbase = sB + (uint32_t)(pc * B_WORDS) * 4;
        cp_async16(dbase + (uint32_t)(srow * LDT + skv) * 4,
                   W2 + (size_t)(n0 + srow) * K_WIDE + gcol + skv);
        cp_commit();
    }

    int buf = 0, pbuf = 2;   // compute buffer; prefetch buffer (= buf+2 mod 3)

#pragma unroll 1
    for (int ch = 0; ch < NCH; ++ch) {
        cp_wait1();          // chunk ch's group complete (ch+1 may pend)
        __syncthreads();     // B visible; all warps done with compute(ch-1)

        // ---- stage hs i-group (every 8 chunks) / ht j-block (every 128) ----
        if ((ch & 7) == 0) {
            const int jc = ch >> 7;
            const int ib = (ch >> 3) & 15;
            if ((ch & 127) == 0) {
                // 128 rows x 8 segs = 1024, one per thread
                float4 v = *(const float4*)(ht + (size_t)(m0 + srow) * D_SZ + jc * BKC + skv);
                *(float4*)&Hts[srow * LDT + skv] = v;
            }
            {
                // 8 ii x 128 m = 1024, one per thread
                int ii = tid >> 7;
                int m  = tid & 127;
                Hss[ii * BM + m] = __ldg(hs + (size_t)(m0 + m) * D_SZ + i0 + ib * IPG + ii);
            }
            __syncthreads();
            if ((ch & 127) == 0) {
#pragma unroll
                for (int ks = 0; ks < 4; ++ks) {
                    htr[ks][0] = Hts[(wm + r)     * LDT + ks * 8 + c];
                    htr[ks][1] = Hts[(wm + r + 8) * LDT + ks * 8 + c];
                    htr[ks][2] = Hts[(wm + r)     * LDT + ks * 8 + c + 4];
                    htr[ks][3] = Hts[(wm + r + 8) * LDT + ks * 8 + c + 4];
                }
            }
        }

        // ---- compute chunk ch from Bsm[buf] ----
        {
            const float* Bb = Bsm + buf * B_WORDS;
            const int ii = ch & 7;
            float hsv0 = Hss[ii * BM + wm + r];
            float hsv1 = Hss[ii * BM + wm + r + 8];

#pragma unroll
            for (int ks = 0; ks < 4; ++ks) {
                float a[4];
                a[0] = f2tf32(hsv0 * htr[ks][0]);
                a[1] = f2tf32(hsv1 * htr[ks][1]);
                a[2] = f2tf32(hsv0 * htr[ks][2]);
                a[3] = f2tf32(hsv1 * htr[ks][3]);
#pragma unroll
                for (int ni = 0; ni < 4; ++ni) {
                    int nrow = wn + ni * 8 + r;
                    float b0 = Bb[nrow * LDT + ks * 8 + c];
                    float b1 = Bb[nrow * LDT + ks * 8 + c + 4];
                    mma_tf32(acc[ni], a, b0, b1);
                }
            }
        }

        // ---- issue chunk ch+2 into pbuf (safe: see header comment) ----
        if (ch + 2 < NCH) {
            int cn    = ch + 2;
            int jcn   = cn >> 7;
            int ilocn = ((cn >> 3) & 15) * IPG + (cn & 7);
            size_t gcol = kbase + (size_t)ilocn * D_SZ + jcn * BKC;
            uint32_t dbase = sB + (uint32_t)(pbuf * B_WORDS) * 4;
            cp_async16(dbase + (uint32_t)(srow * LDT + skv) * 4,
                       W2 + (size_t)(n0 + srow) * K_WIDE + gcol + skv);
        }
        cp_commit();   // exactly one group per iteration (possibly empty)

        buf  = (buf  == NBUF - 1) ? 0 : buf + 1;
        pbuf = (pbuf == NBUF - 1) ? 0 : pbuf + 1;
    }

    // ---- epilogue: atomic accumulate onto bias-initialized out[:,768:1536] ----
#pragma unroll
    for (int ni = 0; ni < 4; ++ni) {
        int row = m0 + wm + r;
        int col = N_OUT + n0 + wn + ni * 8 + 2 * c;
        float* p0 = &out[(size_t)row * OUT_STR + col];
        atomicAdd(p0,     acc[ni][0]);
        atomicAdd(p0 + 1, acc[ni][1]);
        float* p1 = &out[(size_t)(row + 8) * OUT_STR + col];
        atomicAdd(p1,     acc[ni][2]);
        atomicAdd(p1 + 1, acc[ni][3]);
    }
}

// ---------------------------------------------------------------------------
extern "C" void kernel_launch(void* const* d_in, const int* in_sizes, int n_in,
                              void* d_out, int out_size)
{
    const float* hs  = (const float*)d_in[0];
    const float* ht  = (const float*)d_in[1];
    const float* WL  = (const float*)d_in[2];
    const float* bL  = (const float*)d_in[3];
    const float* W2  = (const float*)d_in[4];
    const float* bL2 = (const float*)d_in[5];
    float* out = (float*)d_out;

    // deep path + bias init of wide region (same-stream ordering -> graph edge)
    deep_kernel<<<dim3(BATCH / DBM, N_OUT / DBN), 256>>>(hs, ht, WL, bL, bL2, out);

    // dynamic smem (~78 KB > 48 KB static limit); attribute set is not an alloc
    cudaFuncSetAttribute(wide_kernel, cudaFuncAttributeMaxDynamicSharedMemorySize, SMEM_BYTES);

    // wide path: M fastest -> 8 co-scheduled M-CTAs share W2 slices in L2
    wide_kernel<<<dim3(BATCH / BM, N_OUT / BN, KSPLIT), NTH, SMEM_BYTES>>>(hs, ht, W2, out);
}

// round 8
// speedup vs baseline: 1.1201x; 1.1201x over previous
#include <cuda_runtime.h>
#include <cstdint>

// ---------------------------------------------------------------------------
// Problem constants
// ---------------------------------------------------------------------------
#define BATCH   1024
#define D_SZ    384
#define K_WIDE  (D_SZ * D_SZ)      // 147456
#define N_OUT   (2 * D_SZ)         // 768
#define OUT_STR (4 * D_SZ)         // 1536

// ---------------------------------------------------------------------------
// Wide-path GEMM config: M=1024 N=768 K=147456, A = hs x ht generated on-fly
// ---------------------------------------------------------------------------
#define BM      128
#define BN      128
#define BKC     32                  // k-floats per chunk
#define KSPLIT  3
#define KSLICE  (K_WIDE / KSPLIT)   // 49152 = 128 i-values
#define IPG     8                   // i-values per hs staging group
#define NCH     (KSLICE / BKC)      // 1536 chunks per CTA
#define LDT     36                  // row stride words: BKC=32 + 4 pad (conflict-free)
#define NTH     512
#define NBUF    3

// Truncation-bias compensation (this round's change):
// tcgen05 is unavailable (ptxas targets compute_103 without 'a'), and the
// legacy-MMA path was CVT-serialized: 128 cvt.rna.tf32 per SMSP per chunk in
// EVERY config tried (R5/R6/R7 all ~1700 cyc/chunk). We drop the CVTs and let
// the MMA HW truncate both fp32 operands to tf32. Truncation has coherent
// relative bias E[loss] ~= 0.5 * 2^-10 * ln2 per operand; pre-scaling hs by
// (1 + 2 * 0.5 * 2^-10 * ln2) cancels the expected bias of BOTH operands in
// each product, leaving zero-mean noise (~3e-4).
#define HS_COMP 1.000677f

#define B_WORDS   (BN * LDT)            // per B buffer
#define HTS_WORDS (BM * LDT)
#define HSS_WORDS (IPG * BM)
#define SMEM_WORDS (NBUF * B_WORDS + HTS_WORDS + HSS_WORDS)
#define SMEM_BYTES (SMEM_WORDS * 4)     // ~78 KB -> dynamic smem

__device__ __forceinline__ void cp_async16(uint32_t dst, const void* src) {
    asm volatile("cp.async.cg.shared.global [%0], [%1], 16;" :: "r"(dst), "l"(src) : "memory");
}
__device__ __forceinline__ void cp_commit() {
    asm volatile("cp.async.commit_group;" ::: "memory");
}
__device__ __forceinline__ void cp_wait1() {
    asm volatile("cp.async.wait_group 1;" ::: "memory");
}
__device__ __forceinline__ uint32_t smem_u32(const void* p) {
    uint32_t a;
    asm("{ .reg .u64 t; cvta.to.shared.u64 t, %1; cvt.u32.u64 %0, t; }" : "=r"(a) : "l"(p));
    return a;
}

// m16n8k8 tf32 mma; BOTH operands HW-truncated from fp32 bits (bias
// compensated via HS_COMP at staging; no per-chunk CVT instructions)
__device__ __forceinline__ void mma_tf32(float c[4], const float a[4], float b0, float b1) {
    asm volatile(
        "mma.sync.aligned.m16n8k8.row.col.f32.tf32.tf32.f32 "
        "{%0,%1,%2,%3}, {%4,%5,%6,%7}, {%8,%9}, {%0,%1,%2,%3};\n"
        : "+f"(c[0]), "+f"(c[1]), "+f"(c[2]), "+f"(c[3])
        : "r"(__float_as_uint(a[0])), "r"(__float_as_uint(a[1])),
          "r"(__float_as_uint(a[2])), "r"(__float_as_uint(a[3])),
          "r"(__float_as_uint(b0)), "r"(__float_as_uint(b1)));
}

// ---------------------------------------------------------------------------
// Deep path (passed R1, unchanged):  g = [hs|ht] @ W_L^T + b_L -> out[:,0:768]
// Also initializes out[:,768:1536] = b_L2 for the wide kernel's atomics.
// ---------------------------------------------------------------------------
#define DBM 64
#define DBN 64
#define DBK 16

__global__ __launch_bounds__(256)
void deep_kernel(const float* __restrict__ hs, const float* __restrict__ ht,
                 const float* __restrict__ WL, const float* __restrict__ bL,
                 const float* __restrict__ bL2, float* __restrict__ out)
{
    __shared__ float Xs[DBK][DBM + 8];
    __shared__ float Ws[DBK][DBN + 8];

    const int tid = threadIdx.x;
    const int tx  = tid & 15;
    const int ty  = tid >> 4;
    const int m0  = blockIdx.x * DBM;
    const int n0  = blockIdx.y * DBN;

    float acc[4][4];
#pragma unroll
    for (int i = 0; i < 4; ++i)
#pragma unroll
        for (int j = 0; j < 4; ++j) acc[i][j] = 0.f;

    for (int k0 = 0; k0 < 2 * D_SZ; k0 += DBK) {
        __syncthreads();
#pragma unroll
        for (int q = 0; q < 4; ++q) {
            int e  = tid + 256 * q;
            int kk = e & 15;
            int mm = e >> 4;
            int gk = k0 + kk;
            float xv = (gk < D_SZ) ? hs[(m0 + mm) * D_SZ + gk]
                                   : ht[(m0 + mm) * D_SZ + (gk - D_SZ)];
            Xs[kk][mm] = xv;
            Ws[kk][mm] = WL[(size_t)(n0 + mm) * (2 * D_SZ) + gk];
        }
        __syncthreads();
#pragma unroll
        for (int kk = 0; kk < DBK; ++kk) {
            float4 av = *(const float4*)&Xs[kk][ty * 4];
            float4 bv = *(const float4*)&Ws[kk][tx * 4];
            float a[4] = {av.x, av.y, av.z, av.w};
            float b[4] = {bv.x, bv.y, bv.z, bv.w};
#pragma unroll
            for (int i = 0; i < 4; ++i)
#pragma unroll
                for (int j = 0; j < 4; ++j) acc[i][j] += a[i] * b[j];
        }
    }

#pragma unroll
    for (int i = 0; i < 4; ++i) {
        int row = m0 + ty * 4 + i;
#pragma unroll
        for (int j = 0; j < 4; ++j) {
            int col = n0 + tx * 4 + j;
            out[(size_t)row * OUT_STR + col]         = acc[i][j] + bL[col];
            out[(size_t)row * OUT_STR + N_OUT + col] = bL2[col];
        }
    }
}

// ---------------------------------------------------------------------------
// Wide kernel: 512 threads = 16 warps (4m x 4n), warp tile 32x32.
// (R5 structure verbatim — best known — with per-chunk CVTs removed.)
// A fragments: ht frags (per 128-chunk j-block, registers) x hs scalars
// (per 8-chunk i-group, SMEM, pre-scaled by HS_COMP).
// B: 3-buffer cp.async ring.
// Pipeline per chunk ch: wait_group 1 (ch landed) -> sync -> compute buf(ch%3)
// -> issue ch+2 into buf((ch+2)%3) -> commit. Issue target last read at
// iteration ch-1; the barrier at top of ch bounds warp drift.
// ---------------------------------------------------------------------------
__global__ __launch_bounds__(NTH, 1)
void wide_kernel(const float* __restrict__ hs, const float* __restrict__ ht,
                 const float* __restrict__ W2, float* __restrict__ out)
{
    extern __shared__ __align__(16) float smem[];
    float* Bsm = smem;                          // NBUF * BN * LDT
    float* Hts = smem + NBUF * B_WORDS;         // BM * LDT
    float* Hss = Hts + HTS_WORDS;               // IPG * BM

    const int tid  = threadIdx.x;
    const int lane = tid & 31;
    const int warp = tid >> 5;
    const int wm = (warp & 3) * 32;     // warp m offset
    const int wn = (warp >> 2) * 32;    // warp n offset
    const int r  = lane >> 2;           // 0..7
    const int c  = lane & 3;            // 0..3

    const int m0 = blockIdx.x * BM;
    const int n0 = blockIdx.y * BN;
    const int z  = blockIdx.z;
    const size_t kbase = (size_t)z * KSLICE;
    const int i0 = z * (KSLICE / D_SZ);

    // per-thread B staging coords (128 rows x 8 float4-segs = 1024 segs, 2 each)
    const int srow0 = (tid * 2)     >> 3;
    const int skv0  = ((tid * 2)     & 7) * 4;
    const int srow1 = (tid * 2 + 1) >> 3;
    const int skv1  = ((tid * 2 + 1) & 7) * 4;
    const uint32_t sB = smem_u32(Bsm);

    float acc[2][4][4];
#pragma unroll
    for (int mi = 0; mi < 2; ++mi)
#pragma unroll
        for (int ni = 0; ni < 4; ++ni)
#pragma unroll
            for (int q = 0; q < 4; ++q) acc[mi][ni][q] = 0.f;

    float htr[4][2][4];   // ht fragments [kstep][mi][frag]

    // ---- prologue: issue chunks 0 and 1 (jc=0, i_loc=pc) ----
#pragma unroll
    for (int pc = 0; pc < 2; ++pc) {
        size_t gcol = kbase + (size_t)pc * D_SZ;
        uint32_t dbase = sB + (uint32_t)(pc * B_WORDS) * 4;
        cp_async16(dbase + (uint32_t)(srow0 * LDT + skv0) * 4,
                   W2 + (size_t)(n0 + srow0) * K_WIDE + gcol + skv0);
        cp_async16(dbase + (uint32_t)(srow1 * LDT + skv1) * 4,
                   W2 + (size_t)(n0 + srow1) * K_WIDE + gcol + skv1);
        cp_commit();
    }

    int buf = 0, pbuf = 2;   // compute buffer; prefetch buffer (= buf+2 mod 3)

#pragma unroll 1
    for (int ch = 0; ch < NCH; ++ch) {
        cp_wait1();          // chunk ch's group complete (ch+1 may pend)
        __syncthreads();     // B visible; all warps done with compute(ch-1)

        // ---- stage hs i-group (every 8 chunks) / ht j-block (every 128) ----
        if ((ch & 7) == 0) {
            const int jc = ch >> 7;
            const int ib = (ch >> 3) & 15;
            if ((ch & 127) == 0) {
#pragma unroll
                for (int s = 0; s < 2; ++s) {
                    int seg = tid * 2 + s;
                    int row = seg >> 3;
                    int kv  = (seg & 7) * 4;
                    float4 v = *(const float4*)(ht + (size_t)(m0 + row) * D_SZ + jc * BKC + kv);
                    *(float4*)&Hts[row * LDT + kv] = v;
                }
            }
#pragma unroll
            for (int s = 0; s < 2; ++s) {
                int e  = tid + NTH * s;
                int ii = e >> 7;
                int m  = e & 127;
                // HS_COMP: cancels expected tf32-truncation bias of both mma operands
                Hss[ii * BM + m] = __ldg(hs + (size_t)(m0 + m) * D_SZ + i0 + ib * IPG + ii) * HS_COMP;
            }
            __syncthreads();
            if ((ch & 127) == 0) {
#pragma unroll
                for (int ks = 0; ks < 4; ++ks)
#pragma unroll
                    for (int mi = 0; mi < 2; ++mi) {
                        int mrow = wm + mi * 16;
                        htr[ks][mi][0] = Hts[(mrow + r)     * LDT + ks * 8 + c];
                        htr[ks][mi][1] = Hts[(mrow + r + 8) * LDT + ks * 8 + c];
                        htr[ks][mi][2] = Hts[(mrow + r)     * LDT + ks * 8 + c + 4];
                        htr[ks][mi][3] = Hts[(mrow + r + 8) * LDT + ks * 8 + c + 4];
                    }
            }
        }

        // ---- compute chunk ch from Bsm[buf] (no CVTs: HW truncation) ----
        {
            const float* Bb = Bsm + buf * B_WORDS;
            const int ii = ch & 7;
            float hsv[2][2];
            hsv[0][0] = Hss[ii * BM + wm + r];
            hsv[0][1] = Hss[ii * BM + wm + r + 8];
            hsv[1][0] = Hss[ii * BM + wm + 16 + r];
            hsv[1][1] = Hss[ii * BM + wm + 16 + r + 8];

#pragma unroll
            for (int ks = 0; ks < 4; ++ks) {
                float a[2][4];
#pragma unroll
                for (int mi = 0; mi < 2; ++mi) {
                    a[mi][0] = hsv[mi][0] * htr[ks][mi][0];
                    a[mi][1] = hsv[mi][1] * htr[ks][mi][1];
                    a[mi][2] = hsv[mi][0] * htr[ks][mi][2];
                    a[mi][3] = hsv[mi][1] * htr[ks][mi][3];
                }
#pragma unroll
                for (int ni = 0; ni < 4; ++ni) {
                    int nrow = wn + ni * 8 + r;
                    float b0 = Bb[nrow * LDT + ks * 8 + c];
                    float b1 = Bb[nrow * LDT + ks * 8 + c + 4];
                    mma_tf32(acc[0][ni], a[0], b0, b1);
                    mma_tf32(acc[1][ni], a[1], b0, b1);
                }
            }
        }

        // ---- issue chunk ch+2 into pbuf (safe: see header comment) ----
        if (ch + 2 < NCH) {
            int cn    = ch + 2;
            int jcn   = cn >> 7;
            int ilocn = ((cn >> 3) & 15) * IPG + (cn & 7);
            size_t gcol = kbase + (size_t)ilocn * D_SZ + jcn * BKC;
            uint32_t dbase = sB + (uint32_t)(pbuf * B_WORDS) * 4;
            cp_async16(dbase + (uint32_t)(srow0 * LDT + skv0) * 4,
                       W2 + (size_t)(n0 + srow0) * K_WIDE + gcol + skv0);
            cp_async16(dbase + (uint32_t)(srow1 * LDT + skv1) * 4,
                       W2 + (size_t)(n0 + srow1) * K_WIDE + gcol + skv1);
        }
        cp_commit();   // exactly one group per iteration (possibly empty)

        buf  = (buf  == NBUF - 1) ? 0 : buf + 1;
        pbuf = (pbuf == NBUF - 1) ? 0 : pbuf + 1;
    }

    // ---- epilogue: atomic accumulate onto bias-initialized out[:,768:1536] ----
#pragma unroll
    for (int mi = 0; mi < 2; ++mi) {
#pragma unroll
        for (int ni = 0; ni < 4; ++ni) {
            int row = m0 + wm + mi * 16 + r;
            int col = N_OUT + n0 + wn + ni * 8 + 2 * c;
            float* p0 = &out[(size_t)row * OUT_STR + col];
            atomicAdd(p0,     acc[mi][ni][0]);
            atomicAdd(p0 + 1, acc[mi][ni][1]);
            float* p1 = &out[(size_t)(row + 8) * OUT_STR + col];
            atomicAdd(p1,     acc[mi][ni][2]);
            atomicAdd(p1 + 1, acc[mi][ni][3]);
        }
    }
}

// ---------------------------------------------------------------------------
extern "C" void kernel_launch(void* const* d_in, const int* in_sizes, int n_in,
                              void* d_out, int out_size)
{
    const float* hs  = (const float*)d_in[0];
    const float* ht  = (const float*)d_in[1];
    const float* WL  = (const float*)d_in[2];
    const float* bL  = (const float*)d_in[3];
    const float* W2  = (const float*)d_in[4];
    const float* bL2 = (const float*)d_in[5];
    float* out = (float*)d_out;

    // deep path + bias init of wide region (same-stream ordering -> graph edge)
    deep_kernel<<<dim3(BATCH / DBM, N_OUT / DBN), 256>>>(hs, ht, WL, bL, bL2, out);

    // dynamic smem (~78 KB > 48 KB static limit); attribute set is not an alloc
    cudaFuncSetAttribute(wide_kernel, cudaFuncAttributeMaxDynamicSharedMemorySize, SMEM_BYTES);

    // wide path: M fastest -> 8 co-scheduled M-CTAs share W2 slices in L2
    wide_kernel<<<dim3(BATCH / BM, N_OUT / BN, KSPLIT), NTH, SMEM_BYTES>>>(hs, ht, W2, out);
}

// round 10
// speedup vs baseline: 1.1531x; 1.0295x over previous
#include <cuda_runtime.h>
#include <cstdint>

// ---------------------------------------------------------------------------
// Problem constants
// ---------------------------------------------------------------------------
#define BATCH   1024
#define D_SZ    384
#define K_WIDE  (D_SZ * D_SZ)      // 147456
#define N_OUT   (2 * D_SZ)         // 768
#define OUT_STR (4 * D_SZ)         // 1536

// ---------------------------------------------------------------------------
// Wide-path GEMM config: M=1024 N=768 K=147456, A = hs x ht generated on-fly
// ---------------------------------------------------------------------------
#define BM      128
#define BN      128
#define BKC     32                  // k-floats per chunk
#define KSPLIT  3
#define KSLICE  (K_WIDE / KSPLIT)   // 49152 = 128 i-values
#define IPG     8                   // i-values per hs staging group
#define NCH     (KSLICE / BKC)      // 1536 chunks per CTA
#define NPAIR   (NCH / 2)           // 768 pipeline iterations (2 chunks each)
#define LDT     36                  // row stride words: BKC=32 + 4 pad (conflict-free)
#define NTH     512
#define NBUF    6                   // 3-deep ring of chunk PAIRS

// Truncation-bias compensation (R8, kept): both mma operands HW-truncate
// fp32->tf32; pre-scaling hs by (1 + 2^-10 * ln2) cancels the expected
// relative bias of BOTH operands in each product. rel_err ~3.4e-4 measured.
#define HS_COMP 1.000677f

#define B_WORDS   (BN * LDT)            // per B chunk buffer (4608 words)
#define HTS_WORDS (BM * LDT)
#define HSS_WORDS (IPG * BM)
#define SMEM_WORDS (NBUF * B_WORDS + HTS_WORDS + HSS_WORDS)
#define SMEM_BYTES (SMEM_WORDS * 4)     // ~133 KB -> dynamic smem, 1 CTA/SM

__device__ __forceinline__ void cp_async16(uint32_t dst, const void* src) {
    asm volatile("cp.async.cg.shared.global [%0], [%1], 16;" :: "r"(dst), "l"(src) : "memory");
}
__device__ __forceinline__ void cp_commit() {
    asm volatile("cp.async.commit_group;" ::: "memory");
}
__device__ __forceinline__ void cp_wait1() {
    asm volatile("cp.async.wait_group 1;" ::: "memory");
}
__device__ __forceinline__ uint32_t smem_u32(const void* p) {
    uint32_t a;
    asm("{ .reg .u64 t; cvta.to.shared.u64 t, %1; cvt.u32.u64 %0, t; }" : "=r"(a) : "l"(p));
    return a;
}

// m16n8k8 tf32 mma; BOTH operands HW-truncated from fp32 bits
__device__ __forceinline__ void mma_tf32(float c[4], const float a[4], float b0, float b1) {
    asm volatile(
        "mma.sync.aligned.m16n8k8.row.col.f32.tf32.tf32.f32 "
        "{%0,%1,%2,%3}, {%4,%5,%6,%7}, {%8,%9}, {%0,%1,%2,%3};\n"
        : "+f"(c[0]), "+f"(c[1]), "+f"(c[2]), "+f"(c[3])
        : "r"(__float_as_uint(a[0])), "r"(__float_as_uint(a[1])),
          "r"(__float_as_uint(a[2])), "r"(__float_as_uint(a[3])),
          "r"(__float_as_uint(b0)), "r"(__float_as_uint(b1)));
}

// ---------------------------------------------------------------------------
// Deep path (passed R1, unchanged):  g = [hs|ht] @ W_L^T + b_L -> out[:,0:768]
// Also initializes out[:,768:1536] = b_L2 for the wide kernel's atomics.
// ---------------------------------------------------------------------------
#define DBM 64
#define DBN 64
#define DBK 16

__global__ __launch_bounds__(256)
void deep_kernel(const float* __restrict__ hs, const float* __restrict__ ht,
                 const float* __restrict__ WL, const float* __restrict__ bL,
                 const float* __restrict__ bL2, float* __restrict__ out)
{
    __shared__ float Xs[DBK][DBM + 8];
    __shared__ float Ws[DBK][DBN + 8];

    const int tid = threadIdx.x;
    const int tx  = tid & 15;
    const int ty  = tid >> 4;
    const int m0  = blockIdx.x * DBM;
    const int n0  = blockIdx.y * DBN;

    float acc[4][4];
#pragma unroll
    for (int i = 0; i < 4; ++i)
#pragma unroll
        for (int j = 0; j < 4; ++j) acc[i][j] = 0.f;

    for (int k0 = 0; k0 < 2 * D_SZ; k0 += DBK) {
        __syncthreads();
#pragma unroll
        for (int q = 0; q < 4; ++q) {
            int e  = tid + 256 * q;
            int kk = e & 15;
            int mm = e >> 4;
            int gk = k0 + kk;
            float xv = (gk < D_SZ) ? hs[(m0 + mm) * D_SZ + gk]
                                   : ht[(m0 + mm) * D_SZ + (gk - D_SZ)];
            Xs[kk][mm] = xv;
            Ws[kk][mm] = WL[(size_t)(n0 + mm) * (2 * D_SZ) + gk];
        }
        __syncthreads();
#pragma unroll
        for (int kk = 0; kk < DBK; ++kk) {
            float4 av = *(const float4*)&Xs[kk][ty * 4];
            float4 bv = *(const float4*)&Ws[kk][tx * 4];
            float a[4] = {av.x, av.y, av.z, av.w};
            float b[4] = {bv.x, bv.y, bv.z, bv.w};
#pragma unroll
            for (int i = 0; i < 4; ++i)
#pragma unroll
                for (int j = 0; j < 4; ++j) acc[i][j] += a[i] * b[j];
        }
    }

#pragma unroll
    for (int i = 0; i < 4; ++i) {
        int row = m0 + ty * 4 + i;
#pragma unroll
        for (int j = 0; j < 4; ++j) {
            int col = n0 + tx * 4 + j;
            out[(size_t)row * OUT_STR + col]         = acc[i][j] + bL[col];
            out[(size_t)row * OUT_STR + N_OUT + col] = bL2[col];
        }
    }
}

// ---------------------------------------------------------------------------
// Wide kernel: 512 threads = 16 warps (4m x 4n), warp tile 32x32.
// R9 change: TWO chunks per pipeline iteration (one cp.async group, one
// wait, one barrier per pair). Pairs (2t,2t+1) always share the same
// j-block (ii innermost, IPG=8, pairs aligned), so htr registers are reused
// and 64 mma chains sit between barriers for ILP.
// Ring: NBUF=6 chunk buffers = 3 pairs. Iter t computes bufs (2t)%6,(2t+1)%6,
// then issues pair t+2 into (2t+4)%6,(2t+5)%6 — last read at iter t-1; the
// barrier at top of iter t bounds warp drift (same safety as the R5 ring).
// ---------------------------------------------------------------------------
__global__ __launch_bounds__(NTH, 1)
void wide_kernel(const float* __restrict__ hs, const float* __restrict__ ht,
                 const float* __restrict__ W2, float* __restrict__ out)
{
    extern __shared__ __align__(16) float smem[];
    float* Bsm = smem;                          // NBUF * BN * LDT
    float* Hts = smem + NBUF * B_WORDS;         // BM * LDT
    float* Hss = Hts + HTS_WORDS;               // IPG * BM

    const int tid  = threadIdx.x;
    const int lane = tid & 31;
    const int warp = tid >> 5;
    const int wm = (warp & 3) * 32;     // warp m offset
    const int wn = (warp >> 2) * 32;    // warp n offset
    const int r  = lane >> 2;           // 0..7
    const int c  = lane & 3;            // 0..3

    const int m0 = blockIdx.x * BM;
    const int n0 = blockIdx.y * BN;
    const int z  = blockIdx.z;
    const size_t kbase = (size_t)z * KSLICE;
    const int i0 = z * (KSLICE / D_SZ);

    // per-thread B staging coords (128 rows x 8 float4-segs = 1024 segs, 2 each)
    const int srow0 = (tid * 2)     >> 3;
    const int skv0  = ((tid * 2)     & 7) * 4;
    const int srow1 = (tid * 2 + 1) >> 3;
    const int skv1  = ((tid * 2 + 1) & 7) * 4;
    const uint32_t sB = smem_u32(Bsm);

    float acc[2][4][4];
#pragma unroll
    for (int mi = 0; mi < 2; ++mi)
#pragma unroll
        for (int ni = 0; ni < 4; ++ni)
#pragma unroll
            for (int q = 0; q < 4; ++q) acc[mi][ni][q] = 0.f;

    float htr[4][2][4];   // ht fragments [kstep][mi][frag], per j-block

    // ---- prologue: issue pairs 0 and 1 (chunks 0..3; jc=0, i_loc=chunk) ----
#pragma unroll
    for (int pp = 0; pp < 2; ++pp) {
#pragma unroll
        for (int s = 0; s < 2; ++s) {
            int pc = pp * 2 + s;                    // chunk 0..3
            size_t gcol = kbase + (size_t)pc * D_SZ;
            uint32_t dbase = sB + (uint32_t)(pc * B_WORDS) * 4;
            cp_async16(dbase + (uint32_t)(srow0 * LDT + skv0) * 4,
                       W2 + (size_t)(n0 + srow0) * K_WIDE + gcol + skv0);
            cp_async16(dbase + (uint32_t)(srow1 * LDT + skv1) * 4,
                       W2 + (size_t)(n0 + srow1) * K_WIDE + gcol + skv1);
        }
        cp_commit();                                // one group per PAIR
    }

    int buf0 = 0;   // first buffer of current pair:  (2t) % 6
    int pbf0 = 4;   // first buffer of prefetch pair: (2t+4) % 6

#pragma unroll 1
    for (int t = 0; t < NPAIR; ++t) {
        const int ch = 2 * t;
        cp_wait1();          // pair t's group complete (pair t+1 may pend)
        __syncthreads();     // B visible; all warps done with iter t-1

        // ---- stage hs i-group (every 4 pairs) / ht j-block (every 64) ----
        if ((ch & 7) == 0) {
            const int jc = ch >> 7;
            const int ib = (ch >> 3) & 15;
            if ((ch & 127) == 0) {
#pragma unroll
                for (int s = 0; s < 2; ++s) {
                    int seg = tid * 2 + s;
                    int row = seg >> 3;
                    int kv  = (seg & 7) * 4;
                    float4 v = *(const float4*)(ht + (size_t)(m0 + row) * D_SZ + jc * BKC + kv);
                    *(float4*)&Hts[row * LDT + kv] = v;
                }
            }
#pragma unroll
            for (int s = 0; s < 2; ++s) {
                int e  = tid + NTH * s;
                int ii = e >> 7;
                int m  = e & 127;
                // HS_COMP cancels expected tf32-truncation bias of both operands
                Hss[ii * BM + m] = __ldg(hs + (size_t)(m0 + m) * D_SZ + i0 + ib * IPG + ii) * HS_COMP;
            }
            __syncthreads();
            if ((ch & 127) == 0) {
#pragma unroll
                for (int ks = 0; ks < 4; ++ks)
#pragma unroll
                    for (int mi = 0; mi < 2; ++mi) {
                        int mrow = wm + mi * 16;
                        htr[ks][mi][0] = Hts[(mrow + r)     * LDT + ks * 8 + c];
                        htr[ks][mi][1] = Hts[(mrow + r + 8) * LDT + ks * 8 + c];
                        htr[ks][mi][2] = Hts[(mrow + r)     * LDT + ks * 8 + c + 4];
                        htr[ks][mi][3] = Hts[(mrow + r + 8) * LDT + ks * 8 + c + 4];
                    }
            }
        }

        // ---- compute BOTH chunks of pair t (same htr; different hs, B) ----
        const int iibase = ch & 7;          // even; pair is (iibase, iibase+1)
#pragma unroll
        for (int sub = 0; sub < 2; ++sub) {
            const float* Bb = Bsm + (buf0 + sub) * B_WORDS;
            const int ii = iibase + sub;
            float hsv[2][2];
            hsv[0][0] = Hss[ii * BM + wm + r];
            hsv[0][1] = Hss[ii * BM + wm + r + 8];
            hsv[1][0] = Hss[ii * BM + wm + 16 + r];
            hsv[1][1] = Hss[ii * BM + wm + 16 + r + 8];

#pragma unroll
            for (int ks = 0; ks < 4; ++ks) {
                float a[2][4];
#pragma unroll
                for (int mi = 0; mi < 2; ++mi) {
                    a[mi][0] = hsv[mi][0] * htr[ks][mi][0];
                    a[mi][1] = hsv[mi][1] * htr[ks][mi][1];
                    a[mi][2] = hsv[mi][0] * htr[ks][mi][2];
                    a[mi][3] = hsv[mi][1] * htr[ks][mi][3];
                }
#pragma unroll
                for (int ni = 0; ni < 4; ++ni) {
                    int nrow = wn + ni * 8 + r;
                    float b0 = Bb[nrow * LDT + ks * 8 + c];
                    float b1 = Bb[nrow * LDT + ks * 8 + c + 4];
                    mma_tf32(acc[0][ni], a[0], b0, b1);
                    mma_tf32(acc[1][ni], a[1], b0, b1);
                }
            }
        }

        // ---- issue pair t+2 into (pbf0, pbf0+1) (safe: see header) ----
#pragma unroll
        for (int sub = 0; sub < 2; ++sub) {
            int cn = ch + 4 + sub;
            if (cn < NCH) {
                int jcn   = cn >> 7;
                int ilocn = ((cn >> 3) & 15) * IPG + (cn & 7);
                size_t gcol = kbase + (size_t)ilocn * D_SZ + jcn * BKC;
                uint32_t dbase = sB + (uint32_t)((pbf0 + sub) * B_WORDS) * 4;
                cp_async16(dbase + (uint32_t)(srow0 * LDT + skv0) * 4,
                           W2 + (size_t)(n0 + srow0) * K_WIDE + gcol + skv0);
                cp_async16(dbase + (uint32_t)(srow1 * LDT + skv1) * 4,
                           W2 + (size_t)(n0 + srow1) * K_WIDE + gcol + skv1);
            }
        }
        cp_commit();   // exactly one group per iteration (possibly empty)

        buf0 += 2; if (buf0 >= NBUF) buf0 -= NBUF;
        pbf0 += 2; if (pbf0 >= NBUF) pbf0 -= NBUF;
    }

    // ---- epilogue: atomic accumulate onto bias-initialized out[:,768:1536] ----
#pragma unroll
    for (int mi = 0; mi < 2; ++mi) {
#pragma unroll
        for (int ni = 0; ni < 4; ++ni) {
            int row = m0 + wm + mi * 16 + r;
            int col = N_OUT + n0 + wn + ni * 8 + 2 * c;
            float* p0 = &out[(size_t)row * OUT_STR + col];
            atomicAdd(p0,     acc[mi][ni][0]);
            atomicAdd(p0 + 1, acc[mi][ni][1]);
            float* p1 = &out[(size_t)(row + 8) * OUT_STR + col];
            atomicAdd(p1,     acc[mi][ni][2]);
            atomicAdd(p1 + 1, acc[mi][ni][3]);
        }
    }
}

// ---------------------------------------------------------------------------
extern "C" void kernel_launch(void* const* d_in, const int* in_sizes, int n_in,
                              void* d_out, int out_size)
{
    const float* hs  = (const float*)d_in[0];
    const float* ht  = (const float*)d_in[1];
    const float* WL  = (const float*)d_in[2];
    const float* bL  = (const float*)d_in[3];
    const float* W2  = (const float*)d_in[4];
    const float* bL2 = (const float*)d_in[5];
    float* out = (float*)d_out;

    // deep path + bias init of wide region (same-stream ordering -> graph edge)
    deep_kernel<<<dim3(BATCH / DBM, N_OUT / DBN), 256>>>(hs, ht, WL, bL, bL2, out);

    // dynamic smem (~133 KB); attribute set is not an allocation
    cudaFuncSetAttribute(wide_kernel, cudaFuncAttributeMaxDynamicSharedMemorySize, SMEM_BYTES);

    // wide path: M fastest -> 8 co-scheduled M-CTAs share W2 slices in L2
    wide_kernel<<<dim3(BATCH / BM, N_OUT / BN, KSPLIT), NTH, SMEM_BYTES>>>(hs, ht, W2, out);
}